// round 17
// baseline (speedup 1.0000x reference)
#include <cuda_runtime.h>
#include <cuda_bf16.h>
#include <mma.h>
#include <cstddef>
#include <cstdint>

using namespace nvcuda;

#define BATCH 8
#define CIN 64
#define NPTS 4096
#define COUT 64
#define KNN 20
#define QT 128                 // queries per block
#define NTC 64                 // candidates per tile
#define NT (NPTS / NTC)        // 64 tiles

// padded strides (elements)
#define LDA 72                 // bf16 A/B rows: 64 ch + 8 pad (144B, 16B mult)
#define LDD 132                // f32 D col-major: 128 q + 4 pad

// smem byte offsets (all 16B aligned)
#define SA_HI 0
#define SA_LO (SA_HI + QT * LDA * 2)       // 18432
#define SB_HI (SA_LO + QT * LDA * 2)       // 36864
#define SB_LO (SB_HI + NTC * LDA * 2)      // 46080
#define SD    (SB_LO + NTC * LDA * 2)      // 55296
#define SXX   (SD + LDD * NTC * 4)         // 89088
#define SM_TOTAL (SXX + 2 * NTC * 4)       // 89600 (~87.5KB -> 2 blocks/SM, one wave)

// scratch (device globals: no allocations allowed)
__device__ float          g_y2p[(size_t)BATCH * NPTS * COUT];
__device__ float          g_zp [(size_t)BATCH * NPTS * COUT];
__device__ float          g_xx [(size_t)BATCH * NPTS];
__device__ __nv_bfloat16  g_xhi[(size_t)BATCH * NPTS * CIN];  // [b][n][c], 128B rows
__device__ __nv_bfloat16  g_xlo[(size_t)BATCH * NPTS * CIN];

// ---------------------------------------------------------------------------
// Kernel A: projections + BN folding + ||x||^2 + bf16 hi/lo split rows
// ---------------------------------------------------------------------------
__global__ void __launch_bounds__(128) prep_kernel(
    const float* __restrict__ x, const float* __restrict__ W,
    const float* __restrict__ gamma, const float* __restrict__ beta,
    const float* __restrict__ rmean, const float* __restrict__ rvar)
{
    __shared__ float sW[COUT * 2 * CIN];
    __shared__ float sA[COUT], sC0[COUT];

    const int t = threadIdx.x;
    const int b = blockIdx.y;
    const int n = blockIdx.x * 128 + t;

    for (int i = t; i < 2048; i += 128)
        ((float4*)sW)[i] = ((const float4*)W)[i];
    if (t < COUT) {
        float a = rsqrtf(rvar[t] + 1e-5f) * gamma[t];
        sA[t] = a;
        sC0[t] = fmaf(-a, rmean[t], beta[t]);
    }
    __syncthreads();

    const float* xb = x + (size_t)b * CIN * NPTS;
    float xq[CIN];
#pragma unroll
    for (int c = 0; c < CIN; c++) xq[c] = xb[(size_t)c * NPTS + n];

    float xx = 0.f;
#pragma unroll
    for (int c = 0; c < CIN; c++) xx = fmaf(xq[c], xq[c], xx);
    g_xx[(size_t)b * NPTS + n] = xx;

    // bf16 hi/lo split rows [n][c]
    {
        const size_t rb = ((size_t)b * NPTS + n) * CIN;
#pragma unroll
        for (int c = 0; c < CIN; c += 2) {
            __nv_bfloat16 h0 = __float2bfloat16(xq[c]);
            __nv_bfloat16 h1 = __float2bfloat16(xq[c + 1]);
            __nv_bfloat16 l0 = __float2bfloat16(xq[c] - __bfloat162float(h0));
            __nv_bfloat16 l1 = __float2bfloat16(xq[c + 1] - __bfloat162float(h1));
            *(__nv_bfloat162*)(&g_xhi[rb + c]) = __halves2bfloat162(h0, h1);
            *(__nv_bfloat162*)(&g_xlo[rb + c]) = __halves2bfloat162(l0, l1);
        }
    }

    float* y2r = g_y2p + ((size_t)b * NPTS + n) * COUT;
    float* zr  = g_zp  + ((size_t)b * NPTS + n) * COUT;

#pragma unroll 1
    for (int o = 0; o < COUT; o++) {
        const float* wr = sW + o * 128;
        float s2 = 0.f, sz = 0.f;
#pragma unroll
        for (int c = 0; c < 16; c++) {
            float4 w1 = *(const float4*)(wr + c * 4);
            float4 w2 = *(const float4*)(wr + 64 + c * 4);
            float q0 = xq[4*c+0], q1 = xq[4*c+1], q2 = xq[4*c+2], q3 = xq[4*c+3];
            s2 = fmaf(q0, w2.x, s2); sz = fmaf(q0, w1.x - w2.x, sz);
            s2 = fmaf(q1, w2.y, s2); sz = fmaf(q1, w1.y - w2.y, sz);
            s2 = fmaf(q2, w2.z, s2); sz = fmaf(q2, w1.z - w2.z, sz);
            s2 = fmaf(q3, w2.w, s2); sz = fmaf(q3, w1.w - w2.w, sz);
        }
        float a = sA[o];
        y2r[o] = a * s2;
        zr[o]  = fmaf(a, sz, sC0[o]);
    }
}

// ---------------------------------------------------------------------------
// register top-20 insert (validated R5+): ascending-m scan + strict '<'
// reproduces lax.top_k lowest-index tiebreak.
// ---------------------------------------------------------------------------
__device__ __forceinline__ void insert20r(float (&td)[KNN], int (&ti)[KNN],
                                          float& kmax, int& kpos,
                                          float d, int m)
{
#pragma unroll
    for (int k = 0; k < KNN; k++) {
        if (k == kpos) { td[k] = d; ti[k] = m; }
    }
    float mx = -1e30f; int mp = 0;
#pragma unroll
    for (int k = 0; k < KNN; k++) {
        if (td[k] > mx) { mx = td[k]; mp = k; }
    }
    kmax = mx; kpos = mp;
}

// ---------------------------------------------------------------------------
// Kernel B: WMMA (legacy HMMA path — compute_103-safe) distance GEMM with
// split-bf16 (hh + hl + lh) + fused top-20 + gather-max epilogue.
// Block = 128 thr (4 warps) x 128 queries; 64 candidate tiles of 64.
// A [q][c] row-major, B [n][c] as col-major frags (no transposes).
// D stored col-major sD[q + c*LDD] -> conflict-free per-thread scan.
// R17 fix: sxx DOUBLE-BUFFERED (tile&1). R16 raced: epilogue(tile) read sxx
// in the sync2->sync1 window where fast threads already wrote sxx(tile+1).
// Tile+2 reuse of a buffer is fenced by sync1(tile+1) -> no extra barriers.
// ---------------------------------------------------------------------------
__global__ void __launch_bounds__(128) knn_wmma_kernel(float* __restrict__ out)
{
    extern __shared__ char smem[];
    __nv_bfloat16* sa_hi = (__nv_bfloat16*)(smem + SA_HI);
    __nv_bfloat16* sa_lo = (__nv_bfloat16*)(smem + SA_LO);
    __nv_bfloat16* sb_hi = (__nv_bfloat16*)(smem + SB_HI);
    __nv_bfloat16* sb_lo = (__nv_bfloat16*)(smem + SB_LO);
    float*         sd    = (float*)(smem + SD);
    float*         sxx   = (float*)(smem + SXX);   // [2][NTC]

    const int t = threadIdx.x;
    const int w = t >> 5;
    const int b = blockIdx.y;
    const int qbase = blockIdx.x * QT;
    const int n = qbase + t;               // own query

    const char* xh = (const char*)(g_xhi + (size_t)b * NPTS * CIN);
    const char* xl = (const char*)(g_xlo + (size_t)b * NPTS * CIN);
    const float* xxp = g_xx + (size_t)b * NPTS;

    // load A tiles (128 rows x 128B each, hi+lo) into padded smem rows
#pragma unroll
    for (int i = 0; i < 8; i++) {
        const int idx = i * 128 + t;       // 16B chunk id, 0..1023
        const int row = idx >> 3;
        const int c16 = idx & 7;
        const size_t g = (size_t)(qbase + row) * 128 + c16 * 16;
        *(uint4*)((char*)sa_hi + row * (LDA * 2) + c16 * 16) = *(const uint4*)(xh + g);
        *(uint4*)((char*)sa_lo + row * (LDA * 2) + c16 * 16) = *(const uint4*)(xl + g);
    }

    const float xxq = xxp[n];

    float td[KNN]; int ti[KNN];
#pragma unroll
    for (int k = 0; k < KNN; k++) { td[k] = 1e30f; ti[k] = 0; }
    float kmax = 1e30f; int kpos = 0;

#pragma unroll 1
    for (int tile = 0; tile < NT; tile++) {
        const int xbuf = (tile & 1) * NTC;

        // load B tile (64 rows x 128B, hi+lo) + xx slice (double-buffered)
#pragma unroll
        for (int i = 0; i < 4; i++) {
            const int idx = i * 128 + t;   // 0..511
            const int row = idx >> 3;
            const int c16 = idx & 7;
            const size_t g = (size_t)(tile * NTC + row) * 128 + c16 * 16;
            *(uint4*)((char*)sb_hi + row * (LDA * 2) + c16 * 16) = *(const uint4*)(xh + g);
            *(uint4*)((char*)sb_lo + row * (LDA * 2) + c16 * 16) = *(const uint4*)(xl + g);
        }
        if (t < NTC) sxx[xbuf + t] = xxp[tile * NTC + t];
        __syncthreads();

        // WMMA: each warp computes rows [w*32, w*32+32) x all 64 candidates
        {
            wmma::fragment<wmma::accumulator, 16, 16, 16, float> acc[2][4];
#pragma unroll
            for (int mt = 0; mt < 2; mt++)
#pragma unroll
                for (int nt = 0; nt < 4; nt++)
                    wmma::fill_fragment(acc[mt][nt], 0.0f);

            const int m0 = w * 32;
#pragma unroll
            for (int k = 0; k < 4; k++) {
                wmma::fragment<wmma::matrix_a, 16, 16, 16, __nv_bfloat16, wmma::row_major> fah[2], fal[2];
                wmma::fragment<wmma::matrix_b, 16, 16, 16, __nv_bfloat16, wmma::col_major> fbh[4], fbl[4];
#pragma unroll
                for (int mt = 0; mt < 2; mt++) {
                    wmma::load_matrix_sync(fah[mt], sa_hi + (m0 + mt * 16) * LDA + k * 16, LDA);
                    wmma::load_matrix_sync(fal[mt], sa_lo + (m0 + mt * 16) * LDA + k * 16, LDA);
                }
#pragma unroll
                for (int nt = 0; nt < 4; nt++) {
                    wmma::load_matrix_sync(fbh[nt], sb_hi + (nt * 16) * LDA + k * 16, LDA);
                    wmma::load_matrix_sync(fbl[nt], sb_lo + (nt * 16) * LDA + k * 16, LDA);
                }
#pragma unroll
                for (int mt = 0; mt < 2; mt++)
#pragma unroll
                    for (int nt = 0; nt < 4; nt++) {
                        wmma::mma_sync(acc[mt][nt], fah[mt], fbh[nt], acc[mt][nt]);  // hh
                        wmma::mma_sync(acc[mt][nt], fah[mt], fbl[nt], acc[mt][nt]);  // hl
                        wmma::mma_sync(acc[mt][nt], fal[mt], fbh[nt], acc[mt][nt]);  // lh
                    }
            }

            // store D col-major: element (q, c) at sd[q + c*LDD]
#pragma unroll
            for (int mt = 0; mt < 2; mt++)
#pragma unroll
                for (int nt = 0; nt < 4; nt++)
                    wmma::store_matrix_sync(sd + (m0 + mt * 16) + (nt * 16) * LDD,
                                            acc[mt][nt], LDD, wmma::mem_col_major);
        }
        __syncthreads();

        // epilogue: thread t scans its query's 64 distances (conflict-free)
        const float* sxb = sxx + xbuf;
        const int mb = tile * NTC;
#pragma unroll 2
        for (int c = 0; c < NTC; c += 4) {
            const float d0 = sd[t + (c + 0) * LDD];
            const float d1 = sd[t + (c + 1) * LDD];
            const float d2 = sd[t + (c + 2) * LDD];
            const float d3 = sd[t + (c + 3) * LDD];
            const float e0 = fmaf(d0, -2.f, xxq + sxb[c + 0]);
            const float e1 = fmaf(d1, -2.f, xxq + sxb[c + 1]);
            const float e2 = fmaf(d2, -2.f, xxq + sxb[c + 2]);
            const float e3 = fmaf(d3, -2.f, xxq + sxb[c + 3]);
            const float emin = fminf(fminf(e0, e1), fminf(e2, e3));
            if (emin < kmax) {
                if (e0 < kmax) insert20r(td, ti, kmax, kpos, e0, mb + c + 0);
                if (e1 < kmax) insert20r(td, ti, kmax, kpos, e1, mb + c + 1);
                if (e2 < kmax) insert20r(td, ti, kmax, kpos, e2, mb + c + 2);
                if (e3 < kmax) insert20r(td, ti, kmax, kpos, e3, mb + c + 3);
            }
        }
        // sb writes for tile+1 don't conflict with epilogue (reads sd/sxx only);
        // sxx is double-buffered; sd(tile+1) writes are fenced by sync1(tile+1).
    }

    // fused epilogue: out[b][o][n] = leaky(zp[n][o] + max_k y2p[idx_k][o])
    const float* y2b = g_y2p + (size_t)b * NPTS * COUT;
    float4 acc[16];
#pragma unroll
    for (int j = 0; j < 16; j++) acc[j] = make_float4(-1e30f, -1e30f, -1e30f, -1e30f);

#pragma unroll
    for (int k = 0; k < KNN; k++) {
        const float4* row = (const float4*)(y2b + (size_t)ti[k] * COUT);
#pragma unroll
        for (int j = 0; j < 16; j++) {
            float4 v = row[j];
            acc[j].x = fmaxf(acc[j].x, v.x);
            acc[j].y = fmaxf(acc[j].y, v.y);
            acc[j].z = fmaxf(acc[j].z, v.z);
            acc[j].w = fmaxf(acc[j].w, v.w);
        }
    }

    const float4* zr = (const float4*)(g_zp + ((size_t)b * NPTS + n) * COUT);
    float* ob = out + (size_t)b * COUT * NPTS + n;
#pragma unroll
    for (int j = 0; j < 16; j++) {
        float4 z = zr[j];
        float r0 = z.x + acc[j].x; r0 = (r0 >= 0.f) ? r0 : 0.2f * r0;
        float r1 = z.y + acc[j].y; r1 = (r1 >= 0.f) ? r1 : 0.2f * r1;
        float r2 = z.z + acc[j].z; r2 = (r2 >= 0.f) ? r2 : 0.2f * r2;
        float r3 = z.w + acc[j].w; r3 = (r3 >= 0.f) ? r3 : 0.2f * r3;
        ob[(size_t)(4*j+0) * NPTS] = r0;
        ob[(size_t)(4*j+1) * NPTS] = r1;
        ob[(size_t)(4*j+2) * NPTS] = r2;
        ob[(size_t)(4*j+3) * NPTS] = r3;
    }
}

// ---------------------------------------------------------------------------
extern "C" void kernel_launch(void* const* d_in, const int* in_sizes, int n_in,
                              void* d_out, int out_size)
{
    const float* x     = (const float*)d_in[0];
    const float* W     = (const float*)d_in[1];
    const float* gamma = (const float*)d_in[2];
    const float* beta  = (const float*)d_in[3];
    const float* rmean = (const float*)d_in[4];
    const float* rvar  = (const float*)d_in[5];
    float* out = (float*)d_out;

    (void)in_sizes; (void)n_in; (void)out_size;

    static bool attr_set = false;
    if (!attr_set) {
        cudaFuncSetAttribute(knn_wmma_kernel,
                             cudaFuncAttributeMaxDynamicSharedMemorySize, SM_TOTAL);
        attr_set = true;
    }

    prep_kernel<<<dim3(NPTS / 128, BATCH), 128>>>(x, W, gamma, beta, rmean, rvar);
    knn_wmma_kernel<<<dim3(NPTS / QT, BATCH), 128, SM_TOTAL>>>(out);
}